// round 1
// baseline (speedup 1.0000x reference)
#include <cuda_runtime.h>

// Problem constants (hetero SAGEConv, 3 layers, 3 etypes)
#define DIM      64
#define NTYPES   3
#define NLAYERS  3
#define MAXN     100000
#define MAXE     400000

// Scratch: device globals (no runtime allocation allowed).
__device__ float g_h[2][(size_t)MAXN * DIM];           // ping-pong hidden states
__device__ float g_agg[(size_t)NTYPES * MAXN * DIM];   // per-etype mean-aggregated neighbors
__device__ float g_invdeg[NTYPES * MAXN];              // 1/max(deg,1) per (etype, node)

// ---------------------------------------------------------------------------
// Utility: zero a float4 region (grid-stride)
// ---------------------------------------------------------------------------
__global__ void zero_f4(float4* __restrict__ p, size_t n4) {
    size_t i = (size_t)blockIdx.x * blockDim.x + threadIdx.x;
    size_t stride = (size_t)gridDim.x * blockDim.x;
    float4 z = make_float4(0.f, 0.f, 0.f, 0.f);
    for (; i < n4; i += stride) p[i] = z;
}

// ---------------------------------------------------------------------------
// Degree count (as float) into g_invdeg, then invert in-place.
// ---------------------------------------------------------------------------
__global__ void deg_kernel(const int* __restrict__ dst, float* __restrict__ invdeg,
                           int E, int N) {
    int i = blockIdx.x * blockDim.x + threadIdx.x;
    if (i < NTYPES * E) {
        int t = i / E;
        atomicAdd(&invdeg[t * N + dst[i]], 1.0f);
    }
}

__global__ void invert_kernel(float* __restrict__ p, int n) {
    int i = blockIdx.x * blockDim.x + threadIdx.x;
    if (i < n) p[i] = 1.0f / fmaxf(p[i], 1.0f);
}

// ---------------------------------------------------------------------------
// Scatter: agg[t][dst] += h[src] * invdeg[t][dst]   (so agg == mean)
// 16 threads per edge, each handling 4 contiguous dims via float4 load.
// ---------------------------------------------------------------------------
__global__ void scatter_kernel(const float* __restrict__ h,
                               const int* __restrict__ src,
                               const int* __restrict__ dst,
                               const float* __restrict__ invdeg,
                               float* __restrict__ agg,
                               int E, int N) {
    long long tid = (long long)blockIdx.x * blockDim.x + threadIdx.x;
    long long idx = tid >> 4;                    // edge index over [0, 3E)
    if (idx >= (long long)NTYPES * E) return;
    int lane = (int)(tid & 15);
    int t = (int)(idx / E);
    int s = __ldg(&src[idx]);
    int d = __ldg(&dst[idx]);
    float w = __ldg(&invdeg[t * N + d]);
    float4 v = *(const float4*)(h + (size_t)s * DIM + lane * 4);
    float* o = agg + ((size_t)t * N + d) * DIM + lane * 4;
    atomicAdd(o + 0, v.x * w);
    atomicAdd(o + 1, v.y * w);
    atomicAdd(o + 2, v.z * w);
    atomicAdd(o + 3, v.w * w);
}

// ---------------------------------------------------------------------------
// Fused layer GEMM:
//   out[n] = sum_t act( h[n] @ Ws_t  +  mean_t[n] @ Wn_t  +  b_t )
// Block: 256 threads, 64-row tile x 64 cols; 4x4 register tile per thread.
// A sources (h + 3 means) and 6 weight matrices staged through SMEM in
// 16-wide K chunks.
// ---------------------------------------------------------------------------
template <bool RELU>
__global__ __launch_bounds__(256)
void layer_kernel(const float* __restrict__ h,
                  const float* __restrict__ agg,   // [3][N*64]
                  const float* __restrict__ Ws,    // [3][64][64] (k-major rows)
                  const float* __restrict__ Wn,    // [3][64][64]
                  const float* __restrict__ bias,  // [3][64]
                  float* __restrict__ out,
                  int N) {
    __shared__ float sA[4][16][64];  // [source][k][row]   16 KB
    __shared__ float sB[6][16][64];  // [weight][k][col]   24 KB

    const int tid = threadIdx.x;
    const int tx = tid & 15;         // col group (4 cols)
    const int ty = tid >> 4;         // row group (4 rows)
    const int row0 = blockIdx.x * 64;

    float acc[3][4][4];
#pragma unroll
    for (int t = 0; t < 3; t++)
#pragma unroll
        for (int i = 0; i < 4; i++)
#pragma unroll
            for (int j = 0; j < 4; j++) acc[t][i][j] = 0.f;

    const int s_src = tid >> 6;      // 0..3 : which A source this thread loads
    const int r_src = tid & 63;      // row within tile
    const int row_g = row0 + r_src;
    const float* srcp = (s_src == 0)
        ? h + (size_t)row_g * DIM
        : agg + ((size_t)(s_src - 1) * N + row_g) * DIM;

    for (int k0 = 0; k0 < 64; k0 += 16) {
        // ---- load A tiles (transposed: [k][row]) ----
#pragma unroll
        for (int q = 0; q < 4; q++) {
            float4 v = (row_g < N) ? *(const float4*)(srcp + k0 + q * 4)
                                   : make_float4(0.f, 0.f, 0.f, 0.f);
            sA[s_src][q * 4 + 0][r_src] = v.x;
            sA[s_src][q * 4 + 1][r_src] = v.y;
            sA[s_src][q * 4 + 2][r_src] = v.z;
            sA[s_src][q * 4 + 3][r_src] = v.w;
        }
        // ---- load B tiles: 6 matrices x [16][64] ----
        {
            int kk = tid >> 4;       // 0..15
            int c4 = tid & 15;       // 0..15 (float4 granules)
#pragma unroll
            for (int w = 0; w < 6; w++) {
                const float* Wp = (w < 3) ? Ws + (size_t)w * 4096
                                          : Wn + (size_t)(w - 3) * 4096;
                float4 v = *(const float4*)(Wp + (size_t)(k0 + kk) * 64 + c4 * 4);
                *(float4*)&sB[w][kk][c4 * 4] = v;
            }
        }
        __syncthreads();

        // ---- compute ----
#pragma unroll
        for (int kk = 0; kk < 16; kk++) {
            float4 ahv = *(const float4*)&sA[0][kk][ty * 4];
            float ah[4] = {ahv.x, ahv.y, ahv.z, ahv.w};
            float am[3][4], bs[3][4], bn[3][4];
#pragma unroll
            for (int t = 0; t < 3; t++) {
                float4 v = *(const float4*)&sA[1 + t][kk][ty * 4];
                am[t][0] = v.x; am[t][1] = v.y; am[t][2] = v.z; am[t][3] = v.w;
                float4 b1 = *(const float4*)&sB[t][kk][tx * 4];
                bs[t][0] = b1.x; bs[t][1] = b1.y; bs[t][2] = b1.z; bs[t][3] = b1.w;
                float4 b2 = *(const float4*)&sB[3 + t][kk][tx * 4];
                bn[t][0] = b2.x; bn[t][1] = b2.y; bn[t][2] = b2.z; bn[t][3] = b2.w;
            }
#pragma unroll
            for (int t = 0; t < 3; t++)
#pragma unroll
                for (int i = 0; i < 4; i++)
#pragma unroll
                    for (int j = 0; j < 4; j++)
                        acc[t][i][j] += ah[i] * bs[t][j] + am[t][i] * bn[t][j];
        }
        __syncthreads();
    }

    // ---- epilogue: bias, activation, cross-relation sum, store ----
    float ov[4][4];
#pragma unroll
    for (int i = 0; i < 4; i++)
#pragma unroll
        for (int j = 0; j < 4; j++) ov[i][j] = 0.f;

#pragma unroll
    for (int t = 0; t < 3; t++) {
        float bj[4];
#pragma unroll
        for (int j = 0; j < 4; j++) bj[j] = __ldg(&bias[t * 64 + tx * 4 + j]);
#pragma unroll
        for (int i = 0; i < 4; i++)
#pragma unroll
            for (int j = 0; j < 4; j++) {
                float v = acc[t][i][j] + bj[j];
                if (RELU) v = fmaxf(v, 0.f);
                ov[i][j] += v;
            }
    }

#pragma unroll
    for (int i = 0; i < 4; i++) {
        int row = row0 + ty * 4 + i;
        if (row < N) {
            float4 v = make_float4(ov[i][0], ov[i][1], ov[i][2], ov[i][3]);
            *(float4*)(out + (size_t)row * DIM + tx * 4) = v;
        }
    }
}

// ---------------------------------------------------------------------------
// Launch
// ---------------------------------------------------------------------------
extern "C" void kernel_launch(void* const* d_in, const int* in_sizes, int n_in,
                              void* d_out, int out_size) {
    const float* feat    = (const float*)d_in[0];
    const float* W_self  = (const float*)d_in[1];
    const float* W_neigh = (const float*)d_in[2];
    const float* bias    = (const float*)d_in[3];
    const int*   src     = (const int*)d_in[4];
    const int*   dst     = (const int*)d_in[5];

    const int N = in_sizes[0] / DIM;       // 100000
    const int E = in_sizes[4] / NTYPES;    // 400000
    float* out = (float*)d_out;

    void *ph, *pa, *pd;
    cudaGetSymbolAddress(&ph, g_h);
    cudaGetSymbolAddress(&pa, g_agg);
    cudaGetSymbolAddress(&pd, g_invdeg);
    float* hbuf   = (float*)ph;
    float* agg    = (float*)pa;
    float* invdeg = (float*)pd;

    // degrees (constant across layers)
    {
        size_t n = (size_t)NTYPES * N;                 // 300k floats
        size_t n4 = n / 4;                             // divisible (N*3 % 4 == 0 for 100000*3=300000)
        zero_f4<<<(int)((n4 + 255) / 256), 256>>>((float4*)invdeg, n4);
        int tot = NTYPES * E;
        deg_kernel<<<(tot + 255) / 256, 256>>>(dst, invdeg, E, N);
        invert_kernel<<<((int)n + 255) / 256, 256>>>(invdeg, (int)n);
    }

    const float* h_cur = feat;
    const int nblocks_gemm = (N + 63) / 64;
    const long long scat_threads = (long long)NTYPES * E * 16;
    const int scat_blocks = (int)((scat_threads + 255) / 256);
    const size_t agg_n4 = (size_t)NTYPES * N * DIM / 4;

    for (int l = 0; l < NLAYERS; l++) {
        zero_f4<<<4096, 256>>>((float4*)agg, agg_n4);
        scatter_kernel<<<scat_blocks, 256>>>(h_cur, src, dst, invdeg, agg, E, N);

        float* h_next = (l == NLAYERS - 1) ? out : hbuf + (size_t)(l & 1) * MAXN * DIM;
        const float* Ws = W_self  + (size_t)l * NTYPES * DIM * DIM;
        const float* Wn = W_neigh + (size_t)l * NTYPES * DIM * DIM;
        const float* bl = bias    + (size_t)l * NTYPES * DIM;

        if (l < NLAYERS - 1)
            layer_kernel<true><<<nblocks_gemm, 256>>>(h_cur, agg, Ws, Wn, bl, h_next, N);
        else
            layer_kernel<false><<<nblocks_gemm, 256>>>(h_cur, agg, Ws, Wn, bl, h_next, N);

        h_cur = h_next;
    }
}

// round 2
// speedup vs baseline: 1.6973x; 1.6973x over previous
#include <cuda_runtime.h>

// Problem constants (hetero SAGEConv, 3 layers, 3 etypes)
#define DIM      64
#define NTYPES   3
#define NLAYERS  3
#define MAXN     100000
#define MAXE     400000
#define NSEG     (NTYPES * MAXN)
#define CHUNK    4096                 // scan chunk: 256 threads x 16 items

// Scratch: device globals (no runtime allocation allowed).
__device__ float g_h[2][(size_t)MAXN * DIM];           // ping-pong hidden states
__device__ float g_agg[(size_t)NTYPES * MAXN * DIM];   // per-etype mean aggregates
__device__ int   g_csr_src[(size_t)NTYPES * MAXE];     // src ids grouped by (etype,dst)
__device__ int   g_off[NSEG + 1];                      // segment offsets
__device__ int   g_cur[NSEG];                          // fill cursors
__device__ int   g_bsums[1024];                        // scan block sums
__device__ float g_wsum[DIM * DIM];                    // sum of last-layer self weights

// ---------------------------------------------------------------------------
// zero int4 region
// ---------------------------------------------------------------------------
__global__ void zero_i4(int4* __restrict__ p, int n4) {
    int i = blockIdx.x * blockDim.x + threadIdx.x;
    if (i < n4) p[i] = make_int4(0, 0, 0, 0);
}

// ---------------------------------------------------------------------------
// CSR build: histogram -> scan -> fill
// ---------------------------------------------------------------------------
__global__ void hist_kernel(const int* __restrict__ dst, int* __restrict__ cnt,
                            int E, int N) {
    int i = blockIdx.x * blockDim.x + threadIdx.x;
    if (i < NTYPES * E) {
        int t = i / E;
        atomicAdd(&cnt[t * N + dst[i]], 1);
    }
}

// per-chunk exclusive scan; writes chunk totals
__global__ __launch_bounds__(256)
void scan1_kernel(const int* __restrict__ in, int* __restrict__ out,
                  int* __restrict__ bsums, int n) {
    __shared__ int sh[256];
    int b = blockIdx.x, t = threadIdx.x;
    int base = b * CHUNK + t * 16;
    int vals[16];
    int sum = 0;
#pragma unroll
    for (int i = 0; i < 16; i++) {
        int idx = base + i;
        int v = (idx < n) ? in[idx] : 0;
        vals[i] = sum;            // exclusive within thread
        sum += v;
    }
    sh[t] = sum;
    __syncthreads();
    // inclusive scan over thread sums (Hillis-Steele)
    for (int off = 1; off < 256; off <<= 1) {
        int v = (t >= off) ? sh[t - off] : 0;
        __syncthreads();
        sh[t] += v;
        __syncthreads();
    }
    int texcl = (t == 0) ? 0 : sh[t - 1];
#pragma unroll
    for (int i = 0; i < 16; i++) {
        int idx = base + i;
        if (idx < n) out[idx] = vals[i] + texcl;
    }
    if (t == 255) bsums[b] = sh[255];
}

__global__ void scan2_kernel(int* __restrict__ bsums, int nb) {
    if (threadIdx.x == 0 && blockIdx.x == 0) {
        int s = 0;
        for (int b = 0; b < nb; b++) { int v = bsums[b]; bsums[b] = s; s += v; }
    }
}

__global__ void scan3_kernel(int* __restrict__ off, int* __restrict__ cur,
                             const int* __restrict__ bsums, int n, int total) {
    int i = blockIdx.x * blockDim.x + threadIdx.x;
    if (i < n) {
        int v = off[i] + bsums[i / CHUNK];
        off[i] = v;
        cur[i] = v;
    }
    if (i == 0) off[n] = total;
}

__global__ void fill_kernel(const int* __restrict__ src, const int* __restrict__ dst,
                            int* __restrict__ cur, int* __restrict__ csr,
                            int E, int N) {
    int i = blockIdx.x * blockDim.x + threadIdx.x;
    if (i < NTYPES * E) {
        int t = i / E;
        int pos = atomicAdd(&cur[t * N + dst[i]], 1);
        csr[pos] = src[i];
    }
}

// ---------------------------------------------------------------------------
// Gather-mean aggregation: 16 lanes per (etype,node) segment, float4 per lane.
// agg[seg*64 + lane*4 ..] = (1/max(deg,1)) * sum_e h[csr[e]]
// ---------------------------------------------------------------------------
__global__ __launch_bounds__(256)
void agg_kernel(const float* __restrict__ h, const int* __restrict__ off,
                const int* __restrict__ csr, float* __restrict__ agg, int nseg) {
    long long gid = (long long)blockIdx.x * blockDim.x + threadIdx.x;
    int seg = (int)(gid >> 4);
    if (seg >= nseg) return;
    int lane = (int)(gid & 15);
    int b = __ldg(&off[seg]);
    int e = __ldg(&off[seg + 1]);
    float4 acc = make_float4(0.f, 0.f, 0.f, 0.f);
    for (int i = b; i < e; i++) {
        int s = __ldg(&csr[i]);
        float4 v = *(const float4*)(h + (size_t)s * DIM + lane * 4);
        acc.x += v.x; acc.y += v.y; acc.z += v.z; acc.w += v.w;
    }
    float w = 1.0f / (float)max(e - b, 1);
    acc.x *= w; acc.y *= w; acc.z *= w; acc.w *= w;
    *(float4*)(agg + (size_t)seg * DIM + lane * 4) = acc;
}

// ---------------------------------------------------------------------------
// sum of 3 self-weight matrices for the last (activation-free) layer
// ---------------------------------------------------------------------------
__global__ void wsum_kernel(const float* __restrict__ Ws, float* __restrict__ wsum) {
    int i = blockIdx.x * blockDim.x + threadIdx.x;
    if (i < DIM * DIM) wsum[i] = Ws[i] + Ws[DIM * DIM + i] + Ws[2 * DIM * DIM + i];
}

// ---------------------------------------------------------------------------
// Fused layer GEMM (with per-relation ReLU):
//   out[n] = sum_t relu( h[n] @ Ws_t + mean_t[n] @ Wn_t + b_t )
// 256 threads, 64x64 tile, 4x4 register tile, 3 accumulator sets.
// ---------------------------------------------------------------------------
__global__ __launch_bounds__(256)
void layer_kernel(const float* __restrict__ h,
                  const float* __restrict__ agg,   // [3][N*64]
                  const float* __restrict__ Ws,    // [3][64][64]
                  const float* __restrict__ Wn,    // [3][64][64]
                  const float* __restrict__ bias,  // [3][64]
                  float* __restrict__ out,
                  int N) {
    __shared__ float sA[4][16][64];
    __shared__ float sB[6][16][64];

    const int tid = threadIdx.x;
    const int tx = tid & 15;
    const int ty = tid >> 4;
    const int row0 = blockIdx.x * 64;

    float acc[3][4][4];
#pragma unroll
    for (int t = 0; t < 3; t++)
#pragma unroll
        for (int i = 0; i < 4; i++)
#pragma unroll
            for (int j = 0; j < 4; j++) acc[t][i][j] = 0.f;

    const int s_src = tid >> 6;
    const int r_src = tid & 63;
    const int row_g = row0 + r_src;
    const float* srcp = (s_src == 0)
        ? h + (size_t)row_g * DIM
        : agg + ((size_t)(s_src - 1) * N + row_g) * DIM;

    for (int k0 = 0; k0 < 64; k0 += 16) {
#pragma unroll
        for (int q = 0; q < 4; q++) {
            float4 v = (row_g < N) ? *(const float4*)(srcp + k0 + q * 4)
                                   : make_float4(0.f, 0.f, 0.f, 0.f);
            sA[s_src][q * 4 + 0][r_src] = v.x;
            sA[s_src][q * 4 + 1][r_src] = v.y;
            sA[s_src][q * 4 + 2][r_src] = v.z;
            sA[s_src][q * 4 + 3][r_src] = v.w;
        }
        {
            int kk = tid >> 4;
            int c4 = tid & 15;
#pragma unroll
            for (int w = 0; w < 6; w++) {
                const float* Wp = (w < 3) ? Ws + (size_t)w * 4096
                                          : Wn + (size_t)(w - 3) * 4096;
                float4 v = *(const float4*)(Wp + (size_t)(k0 + kk) * 64 + c4 * 4);
                *(float4*)&sB[w][kk][c4 * 4] = v;
            }
        }
        __syncthreads();

#pragma unroll
        for (int kk = 0; kk < 16; kk++) {
            float4 ahv = *(const float4*)&sA[0][kk][ty * 4];
            float ah[4] = {ahv.x, ahv.y, ahv.z, ahv.w};
            float am[3][4], bs[3][4], bn[3][4];
#pragma unroll
            for (int t = 0; t < 3; t++) {
                float4 v = *(const float4*)&sA[1 + t][kk][ty * 4];
                am[t][0] = v.x; am[t][1] = v.y; am[t][2] = v.z; am[t][3] = v.w;
                float4 b1 = *(const float4*)&sB[t][kk][tx * 4];
                bs[t][0] = b1.x; bs[t][1] = b1.y; bs[t][2] = b1.z; bs[t][3] = b1.w;
                float4 b2 = *(const float4*)&sB[3 + t][kk][tx * 4];
                bn[t][0] = b2.x; bn[t][1] = b2.y; bn[t][2] = b2.z; bn[t][3] = b2.w;
            }
#pragma unroll
            for (int t = 0; t < 3; t++)
#pragma unroll
                for (int i = 0; i < 4; i++)
#pragma unroll
                    for (int j = 0; j < 4; j++)
                        acc[t][i][j] += ah[i] * bs[t][j] + am[t][i] * bn[t][j];
        }
        __syncthreads();
    }

    float ov[4][4];
#pragma unroll
    for (int i = 0; i < 4; i++)
#pragma unroll
        for (int j = 0; j < 4; j++) ov[i][j] = 0.f;

#pragma unroll
    for (int t = 0; t < 3; t++) {
        float bj[4];
#pragma unroll
        for (int j = 0; j < 4; j++) bj[j] = __ldg(&bias[t * 64 + tx * 4 + j]);
#pragma unroll
        for (int i = 0; i < 4; i++)
#pragma unroll
            for (int j = 0; j < 4; j++)
                ov[i][j] += fmaxf(acc[t][i][j] + bj[j], 0.f);
    }

#pragma unroll
    for (int i = 0; i < 4; i++) {
        int row = row0 + ty * 4 + i;
        if (row < N) {
            *(float4*)(out + (size_t)row * DIM + tx * 4) =
                make_float4(ov[i][0], ov[i][1], ov[i][2], ov[i][3]);
        }
    }
}

// ---------------------------------------------------------------------------
// Last layer (no ReLU): out = h @ Wsum + sum_t mean_t @ Wn_t + sum_t b_t
// Only 4 matmuls; single accumulator set.
// ---------------------------------------------------------------------------
__global__ __launch_bounds__(256)
void layer_last_kernel(const float* __restrict__ h,
                       const float* __restrict__ agg,
                       const float* __restrict__ Wsum,  // [64][64]
                       const float* __restrict__ Wn,    // [3][64][64]
                       const float* __restrict__ bias,  // [3][64]
                       float* __restrict__ out,
                       int N) {
    __shared__ float sA[4][16][64];
    __shared__ float sB[4][16][64];

    const int tid = threadIdx.x;
    const int tx = tid & 15;
    const int ty = tid >> 4;
    const int row0 = blockIdx.x * 64;

    float acc[4][4];
#pragma unroll
    for (int i = 0; i < 4; i++)
#pragma unroll
        for (int j = 0; j < 4; j++) acc[i][j] = 0.f;

    const int s_src = tid >> 6;
    const int r_src = tid & 63;
    const int row_g = row0 + r_src;
    const float* srcp = (s_src == 0)
        ? h + (size_t)row_g * DIM
        : agg + ((size_t)(s_src - 1) * N + row_g) * DIM;

    for (int k0 = 0; k0 < 64; k0 += 16) {
#pragma unroll
        for (int q = 0; q < 4; q++) {
            float4 v = (row_g < N) ? *(const float4*)(srcp + k0 + q * 4)
                                   : make_float4(0.f, 0.f, 0.f, 0.f);
            sA[s_src][q * 4 + 0][r_src] = v.x;
            sA[s_src][q * 4 + 1][r_src] = v.y;
            sA[s_src][q * 4 + 2][r_src] = v.z;
            sA[s_src][q * 4 + 3][r_src] = v.w;
        }
        {
            int kk = tid >> 4;
            int c4 = tid & 15;
#pragma unroll
            for (int w = 0; w < 4; w++) {
                const float* Wp = (w == 0) ? Wsum : Wn + (size_t)(w - 1) * 4096;
                float4 v = *(const float4*)(Wp + (size_t)(k0 + kk) * 64 + c4 * 4);
                *(float4*)&sB[w][kk][c4 * 4] = v;
            }
        }
        __syncthreads();

#pragma unroll
        for (int kk = 0; kk < 16; kk++) {
            float a0[4], am[3][4], bw[4][4];
            float4 v = *(const float4*)&sA[0][kk][ty * 4];
            a0[0] = v.x; a0[1] = v.y; a0[2] = v.z; a0[3] = v.w;
#pragma unroll
            for (int t = 0; t < 3; t++) {
                float4 u = *(const float4*)&sA[1 + t][kk][ty * 4];
                am[t][0] = u.x; am[t][1] = u.y; am[t][2] = u.z; am[t][3] = u.w;
            }
#pragma unroll
            for (int w = 0; w < 4; w++) {
                float4 u = *(const float4*)&sB[w][kk][tx * 4];
                bw[w][0] = u.x; bw[w][1] = u.y; bw[w][2] = u.z; bw[w][3] = u.w;
            }
#pragma unroll
            for (int i = 0; i < 4; i++)
#pragma unroll
                for (int j = 0; j < 4; j++)
                    acc[i][j] += a0[i] * bw[0][j] + am[0][i] * bw[1][j]
                               + am[1][i] * bw[2][j] + am[2][i] * bw[3][j];
        }
        __syncthreads();
    }

    float bj[4];
#pragma unroll
    for (int j = 0; j < 4; j++)
        bj[j] = __ldg(&bias[tx * 4 + j]) + __ldg(&bias[64 + tx * 4 + j])
              + __ldg(&bias[128 + tx * 4 + j]);

#pragma unroll
    for (int i = 0; i < 4; i++) {
        int row = row0 + ty * 4 + i;
        if (row < N) {
            *(float4*)(out + (size_t)row * DIM + tx * 4) =
                make_float4(acc[i][0] + bj[0], acc[i][1] + bj[1],
                            acc[i][2] + bj[2], acc[i][3] + bj[3]);
        }
    }
}

// ---------------------------------------------------------------------------
// Launch
// ---------------------------------------------------------------------------
extern "C" void kernel_launch(void* const* d_in, const int* in_sizes, int n_in,
                              void* d_out, int out_size) {
    const float* feat    = (const float*)d_in[0];
    const float* W_self  = (const float*)d_in[1];
    const float* W_neigh = (const float*)d_in[2];
    const float* bias    = (const float*)d_in[3];
    const int*   src     = (const int*)d_in[4];
    const int*   dst     = (const int*)d_in[5];

    const int N = in_sizes[0] / DIM;       // 100000
    const int E = in_sizes[4] / NTYPES;    // 400000
    const int nseg = NTYPES * N;
    const int totE = NTYPES * E;
    float* out = (float*)d_out;

    void *ph, *pa, *pcsr, *poff, *pcur, *pbs, *pws;
    cudaGetSymbolAddress(&ph, g_h);
    cudaGetSymbolAddress(&pa, g_agg);
    cudaGetSymbolAddress(&pcsr, g_csr_src);
    cudaGetSymbolAddress(&poff, g_off);
    cudaGetSymbolAddress(&pcur, g_cur);
    cudaGetSymbolAddress(&pbs, g_bsums);
    cudaGetSymbolAddress(&pws, g_wsum);
    float* hbuf = (float*)ph;
    float* agg  = (float*)pa;
    int* csr    = (int*)pcsr;
    int* off    = (int*)poff;
    int* cur    = (int*)pcur;
    int* bsums  = (int*)pbs;
    float* wsum = (float*)pws;

    // ---- CSR build (once per call; graph constant across layers) ----
    {
        int n4 = (nseg + 3) / 4;
        zero_i4<<<(n4 + 255) / 256, 256>>>((int4*)cur, n4);            // cur as hist
        hist_kernel<<<(totE + 255) / 256, 256>>>(dst, cur, E, N);
        int nb = (nseg + CHUNK - 1) / CHUNK;
        scan1_kernel<<<nb, 256>>>(cur, off, bsums, nseg);
        scan2_kernel<<<1, 32>>>(bsums, nb);
        scan3_kernel<<<(nseg + 255) / 256, 256>>>(off, cur, bsums, nseg, totE);
        fill_kernel<<<(totE + 255) / 256, 256>>>(src, dst, cur, csr, E, N);
        wsum_kernel<<<(DIM * DIM + 255) / 256, 256>>>(
            W_self + (size_t)(NLAYERS - 1) * NTYPES * DIM * DIM, wsum);
    }

    const int nblocks_gemm = (N + 63) / 64;
    const int agg_blocks = (int)(((long long)nseg * 16 + 255) / 256);

    const float* h_cur = feat;
    for (int l = 0; l < NLAYERS; l++) {
        agg_kernel<<<agg_blocks, 256>>>(h_cur, off, csr, agg, nseg);

        float* h_next = (l == NLAYERS - 1) ? out : hbuf + (size_t)(l & 1) * MAXN * DIM;
        const float* Ws = W_self  + (size_t)l * NTYPES * DIM * DIM;
        const float* Wn = W_neigh + (size_t)l * NTYPES * DIM * DIM;
        const float* bl = bias    + (size_t)l * NTYPES * DIM;

        if (l < NLAYERS - 1)
            layer_kernel<<<nblocks_gemm, 256>>>(h_cur, agg, Ws, Wn, bl, h_next, N);
        else
            layer_last_kernel<<<nblocks_gemm, 256>>>(h_cur, agg, wsum, Wn, bl, out, N);

        h_cur = h_next;
    }
}

// round 3
// speedup vs baseline: 1.9707x; 1.1611x over previous
#include <cuda_runtime.h>
#include <cstdint>

// Problem constants (hetero SAGEConv, 3 layers, 3 etypes)
#define DIM      64
#define NTYPES   3
#define NLAYERS  3
#define MAXN     100000
#define MAXE     400000
#define NSEG     (NTYPES * MAXN)
#define CHUNK    4096                 // scan chunk: 256 threads x 16 items

// Scratch: device globals (no runtime allocation allowed).
__device__ float g_h[2][(size_t)MAXN * DIM];           // ping-pong hidden states
__device__ float g_agg[(size_t)NTYPES * MAXN * DIM];   // per-etype mean aggregates
__device__ int   g_csr_src[(size_t)NTYPES * MAXE];     // src ids grouped by (etype,dst)
__device__ int   g_off[NSEG + 1];                      // segment offsets
__device__ int   g_cur[NSEG];                          // fill cursors
__device__ int   g_bsums[1024];                        // scan block sums
__device__ float g_wsum[DIM * DIM];                    // sum of last-layer self weights

// ---------------------------------------------------------------------------
// tf32 helpers
// ---------------------------------------------------------------------------
__device__ __forceinline__ uint32_t f2tf32(float f) {
    uint32_t u;
    asm("cvt.rna.tf32.f32 %0, %1;" : "=r"(u) : "f"(f));
    return u;
}

__device__ __forceinline__ void mma_tf32(float d[4], const uint32_t a[4],
                                         const uint32_t b[2]) {
    asm volatile(
        "mma.sync.aligned.m16n8k8.row.col.f32.tf32.tf32.f32 "
        "{%0,%1,%2,%3}, {%4,%5,%6,%7}, {%8,%9}, {%0,%1,%2,%3};\n"
        : "+f"(d[0]), "+f"(d[1]), "+f"(d[2]), "+f"(d[3])
        : "r"(a[0]), "r"(a[1]), "r"(a[2]), "r"(a[3]), "r"(b[0]), "r"(b[1]));
}

// ---------------------------------------------------------------------------
// zero int4 region
// ---------------------------------------------------------------------------
__global__ void zero_i4(int4* __restrict__ p, int n4) {
    int i = blockIdx.x * blockDim.x + threadIdx.x;
    if (i < n4) p[i] = make_int4(0, 0, 0, 0);
}

// ---------------------------------------------------------------------------
// CSR build: histogram -> scan -> fill
// ---------------------------------------------------------------------------
__global__ void hist_kernel(const int* __restrict__ dst, int* __restrict__ cnt,
                            int E, int N) {
    int i = blockIdx.x * blockDim.x + threadIdx.x;
    if (i < NTYPES * E) {
        int t = i / E;
        atomicAdd(&cnt[t * N + dst[i]], 1);
    }
}

__global__ __launch_bounds__(256)
void scan1_kernel(const int* __restrict__ in, int* __restrict__ out,
                  int* __restrict__ bsums, int n) {
    __shared__ int sh[256];
    int b = blockIdx.x, t = threadIdx.x;
    int base = b * CHUNK + t * 16;
    int vals[16];
    int sum = 0;
#pragma unroll
    for (int i = 0; i < 16; i++) {
        int idx = base + i;
        int v = (idx < n) ? in[idx] : 0;
        vals[i] = sum;
        sum += v;
    }
    sh[t] = sum;
    __syncthreads();
    for (int off = 1; off < 256; off <<= 1) {
        int v = (t >= off) ? sh[t - off] : 0;
        __syncthreads();
        sh[t] += v;
        __syncthreads();
    }
    int texcl = (t == 0) ? 0 : sh[t - 1];
#pragma unroll
    for (int i = 0; i < 16; i++) {
        int idx = base + i;
        if (idx < n) out[idx] = vals[i] + texcl;
    }
    if (t == 255) bsums[b] = sh[255];
}

// parallel exclusive scan of block sums (nb <= 128)
__global__ void scan2_kernel(int* __restrict__ bsums, int nb) {
    __shared__ int sh[128];
    int t = threadIdx.x;
    int v = (t < nb) ? bsums[t] : 0;
    sh[t] = v;
    __syncthreads();
    for (int off = 1; off < 128; off <<= 1) {
        int u = (t >= off) ? sh[t - off] : 0;
        __syncthreads();
        sh[t] += u;
        __syncthreads();
    }
    if (t < nb) bsums[t] = sh[t] - v;   // exclusive
}

__global__ void scan3_kernel(int* __restrict__ off, int* __restrict__ cur,
                             const int* __restrict__ bsums, int n, int total) {
    int i = blockIdx.x * blockDim.x + threadIdx.x;
    if (i < n) {
        int v = off[i] + bsums[i / CHUNK];
        off[i] = v;
        cur[i] = v;
    }
    if (i == 0) off[n] = total;
}

__global__ void fill_kernel(const int* __restrict__ src, const int* __restrict__ dst,
                            int* __restrict__ cur, int* __restrict__ csr,
                            int E, int N) {
    int i = blockIdx.x * blockDim.x + threadIdx.x;
    if (i < NTYPES * E) {
        int t = i / E;
        int pos = atomicAdd(&cur[t * N + dst[i]], 1);
        csr[pos] = src[i];
    }
}

// ---------------------------------------------------------------------------
// Gather-mean aggregation: 16 lanes per (etype,node) segment, float4 per lane.
// ---------------------------------------------------------------------------
__global__ __launch_bounds__(256)
void agg_kernel(const float* __restrict__ h, const int* __restrict__ off,
                const int* __restrict__ csr, float* __restrict__ agg, int nseg) {
    long long gid = (long long)blockIdx.x * blockDim.x + threadIdx.x;
    int seg = (int)(gid >> 4);
    if (seg >= nseg) return;
    int lane = (int)(gid & 15);
    int b = __ldg(&off[seg]);
    int e = __ldg(&off[seg + 1]);
    float4 acc = make_float4(0.f, 0.f, 0.f, 0.f);
    for (int i = b; i < e; i++) {
        int s = __ldg(&csr[i]);
        float4 v = *(const float4*)(h + (size_t)s * DIM + lane * 4);
        acc.x += v.x; acc.y += v.y; acc.z += v.z; acc.w += v.w;
    }
    float w = 1.0f / (float)max(e - b, 1);
    acc.x *= w; acc.y *= w; acc.z *= w; acc.w *= w;
    *(float4*)(agg + (size_t)seg * DIM + lane * 4) = acc;
}

// ---------------------------------------------------------------------------
// sum of 3 self-weight matrices for the last (activation-free) layer
// ---------------------------------------------------------------------------
__global__ void wsum_kernel(const float* __restrict__ Ws, float* __restrict__ wsum) {
    int i = blockIdx.x * blockDim.x + threadIdx.x;
    if (i < DIM * DIM) wsum[i] = Ws[i] + Ws[DIM * DIM + i] + Ws[2 * DIM * DIM + i];
}

// ---------------------------------------------------------------------------
// Hidden layer on tensor cores (tf32 mma.sync, fp32 accumulate):
//   out[n] = sum_t relu( h[n] @ Ws_t + mean_t[n] @ Wn_t + b_t )
// Block: 256 threads (8 warps, 2x4 grid), tile 64 rows x 64 cols.
// Warp (wy,wx): rows [wy*32,+32), cols [wx*16,+16), all 3 relations.
// ---------------------------------------------------------------------------
__global__ __launch_bounds__(256, 2)
void layer_tc_kernel(const float* __restrict__ h,
                     const float* __restrict__ agg,   // [3][N*64]
                     const float* __restrict__ Ws,    // [3][64][64]
                     const float* __restrict__ Wn,    // [3][64][64]
                     const float* __restrict__ bias,  // [3][64]
                     float* __restrict__ out,
                     int N) {
    __shared__ uint32_t sA[4][64][8];   // [src][row][kk]      8 KB
    __shared__ uint32_t sB[6][64][9];   // [mat][col][kk pad]  13.5 KB

    const int tid = threadIdx.x;
    const int lane = tid & 31;
    const int warp = tid >> 5;
    const int wy = warp >> 2;      // 0..1
    const int wx = warp & 3;       // 0..3
    const int lr = lane >> 2;      // 0..7
    const int lc = lane & 3;       // 0..3
    const int row0 = blockIdx.x * 64;

    float acc[3][2][2][4];
#pragma unroll
    for (int t = 0; t < 3; t++)
#pragma unroll
        for (int rt = 0; rt < 2; rt++)
#pragma unroll
            for (int ct = 0; ct < 2; ct++)
#pragma unroll
                for (int q = 0; q < 4; q++) acc[t][rt][ct][q] = 0.f;

    const int s_src = tid >> 6;
    const int r_src = tid & 63;
    const int row_g = row0 + r_src;
    const bool rowok = row_g < N;
    const float* srcp = (s_src == 0)
        ? h + (size_t)row_g * DIM
        : agg + ((size_t)(s_src - 1) * N + row_g) * DIM;

    for (int k0 = 0; k0 < 64; k0 += 8) {
        // ---- stage A: 4 sources x 64 rows x 8 k ----
        float4 v0 = rowok ? *(const float4*)(srcp + k0)
                          : make_float4(0.f, 0.f, 0.f, 0.f);
        float4 v1 = rowok ? *(const float4*)(srcp + k0 + 4)
                          : make_float4(0.f, 0.f, 0.f, 0.f);
        sA[s_src][r_src][0] = f2tf32(v0.x);
        sA[s_src][r_src][1] = f2tf32(v0.y);
        sA[s_src][r_src][2] = f2tf32(v0.z);
        sA[s_src][r_src][3] = f2tf32(v0.w);
        sA[s_src][r_src][4] = f2tf32(v1.x);
        sA[s_src][r_src][5] = f2tf32(v1.y);
        sA[s_src][r_src][6] = f2tf32(v1.z);
        sA[s_src][r_src][7] = f2tf32(v1.w);

        // ---- stage B: 6 mats x 8 kk x 64 cols (transposed to [col][kk]) ----
#pragma unroll
        for (int p = 0; p < 3; p++) {
            int idx = p * 256 + tid;       // < 768
            int w   = idx >> 7;            // 0..5
            int r   = idx & 127;
            int kk  = r & 7;
            int c4  = r >> 3;              // 0..15
            const float* Wp = (w < 3) ? Ws + (size_t)w * 4096
                                      : Wn + (size_t)(w - 3) * 4096;
            float4 bv = *(const float4*)(Wp + (size_t)(k0 + kk) * 64 + c4 * 4);
            sB[w][c4 * 4 + 0][kk] = f2tf32(bv.x);
            sB[w][c4 * 4 + 1][kk] = f2tf32(bv.y);
            sB[w][c4 * 4 + 2][kk] = f2tf32(bv.z);
            sB[w][c4 * 4 + 3][kk] = f2tf32(bv.w);
        }
        __syncthreads();

        // ---- A fragments for h ----
        uint32_t ah[2][4];
#pragma unroll
        for (int rt = 0; rt < 2; rt++) {
            int r = wy * 32 + rt * 16 + lr;
            ah[rt][0] = sA[0][r][lc];
            ah[rt][1] = sA[0][r + 8][lc];
            ah[rt][2] = sA[0][r][lc + 4];
            ah[rt][3] = sA[0][r + 8][lc + 4];
        }
        // ---- self-weight MMAs ----
#pragma unroll
        for (int t = 0; t < 3; t++) {
            uint32_t bs[2][2];
#pragma unroll
            for (int ct = 0; ct < 2; ct++) {
                int c = wx * 16 + ct * 8 + lr;
                bs[ct][0] = sB[t][c][lc];
                bs[ct][1] = sB[t][c][lc + 4];
            }
#pragma unroll
            for (int rt = 0; rt < 2; rt++)
#pragma unroll
                for (int ct = 0; ct < 2; ct++)
                    mma_tf32(acc[t][rt][ct], ah[rt], bs[ct]);
        }
        // ---- neighbor-weight MMAs ----
#pragma unroll
        for (int t = 0; t < 3; t++) {
            uint32_t am[2][4];
#pragma unroll
            for (int rt = 0; rt < 2; rt++) {
                int r = wy * 32 + rt * 16 + lr;
                am[rt][0] = sA[1 + t][r][lc];
                am[rt][1] = sA[1 + t][r + 8][lc];
                am[rt][2] = sA[1 + t][r][lc + 4];
                am[rt][3] = sA[1 + t][r + 8][lc + 4];
            }
            uint32_t bn[2][2];
#pragma unroll
            for (int ct = 0; ct < 2; ct++) {
                int c = wx * 16 + ct * 8 + lr;
                bn[ct][0] = sB[3 + t][c][lc];
                bn[ct][1] = sB[3 + t][c][lc + 4];
            }
#pragma unroll
            for (int rt = 0; rt < 2; rt++)
#pragma unroll
                for (int ct = 0; ct < 2; ct++)
                    mma_tf32(acc[t][rt][ct], am[rt], bn[ct]);
        }
        __syncthreads();
    }

    // ---- epilogue: bias + relu per relation, sum, store ----
#pragma unroll
    for (int rt = 0; rt < 2; rt++) {
#pragma unroll
        for (int ct = 0; ct < 2; ct++) {
            int c0 = wx * 16 + ct * 8 + lc * 2;
            float ov[4] = {0.f, 0.f, 0.f, 0.f};
#pragma unroll
            for (int t = 0; t < 3; t++) {
                float b0 = __ldg(&bias[t * 64 + c0]);
                float b1 = __ldg(&bias[t * 64 + c0 + 1]);
                ov[0] += fmaxf(acc[t][rt][ct][0] + b0, 0.f);
                ov[1] += fmaxf(acc[t][rt][ct][1] + b1, 0.f);
                ov[2] += fmaxf(acc[t][rt][ct][2] + b0, 0.f);
                ov[3] += fmaxf(acc[t][rt][ct][3] + b1, 0.f);
            }
            int r0 = row0 + wy * 32 + rt * 16 + lr;
            if (r0 < N)
                *(float2*)(out + (size_t)r0 * DIM + c0) = make_float2(ov[0], ov[1]);
            if (r0 + 8 < N)
                *(float2*)(out + (size_t)(r0 + 8) * DIM + c0) = make_float2(ov[2], ov[3]);
        }
    }
}

// ---------------------------------------------------------------------------
// Last layer (no ReLU): out = h @ Wsum + sum_t mean_t @ Wn_t + sum_t b_t
// ---------------------------------------------------------------------------
__global__ __launch_bounds__(256, 2)
void layer_last_tc_kernel(const float* __restrict__ h,
                          const float* __restrict__ agg,
                          const float* __restrict__ Wsum,  // [64][64]
                          const float* __restrict__ Wn,    // [3][64][64]
                          const float* __restrict__ bias,  // [3][64]
                          float* __restrict__ out,
                          int N) {
    __shared__ uint32_t sA[4][64][8];
    __shared__ uint32_t sB[4][64][9];

    const int tid = threadIdx.x;
    const int lane = tid & 31;
    const int warp = tid >> 5;
    const int wy = warp >> 2;
    const int wx = warp & 3;
    const int lr = lane >> 2;
    const int lc = lane & 3;
    const int row0 = blockIdx.x * 64;

    float acc[2][2][4];
#pragma unroll
    for (int rt = 0; rt < 2; rt++)
#pragma unroll
        for (int ct = 0; ct < 2; ct++)
#pragma unroll
            for (int q = 0; q < 4; q++) acc[rt][ct][q] = 0.f;

    const int s_src = tid >> 6;
    const int r_src = tid & 63;
    const int row_g = row0 + r_src;
    const bool rowok = row_g < N;
    const float* srcp = (s_src == 0)
        ? h + (size_t)row_g * DIM
        : agg + ((size_t)(s_src - 1) * N + row_g) * DIM;

    for (int k0 = 0; k0 < 64; k0 += 8) {
        float4 v0 = rowok ? *(const float4*)(srcp + k0)
                          : make_float4(0.f, 0.f, 0.f, 0.f);
        float4 v1 = rowok ? *(const float4*)(srcp + k0 + 4)
                          : make_float4(0.f, 0.f, 0.f, 0.f);
        sA[s_src][r_src][0] = f2tf32(v0.x);
        sA[s_src][r_src][1] = f2tf32(v0.y);
        sA[s_src][r_src][2] = f2tf32(v0.z);
        sA[s_src][r_src][3] = f2tf32(v0.w);
        sA[s_src][r_src][4] = f2tf32(v1.x);
        sA[s_src][r_src][5] = f2tf32(v1.y);
        sA[s_src][r_src][6] = f2tf32(v1.z);
        sA[s_src][r_src][7] = f2tf32(v1.w);

        // stage B: 4 mats x 8 kk x 16 float4 = 512 items, 2 per thread
#pragma unroll
        for (int p = 0; p < 2; p++) {
            int idx = p * 256 + tid;       // < 512
            int w   = idx >> 7;            // 0..3
            int r   = idx & 127;
            int kk  = r & 7;
            int c4  = r >> 3;
            const float* Wp = (w == 0) ? Wsum : Wn + (size_t)(w - 1) * 4096;
            float4 bv = *(const float4*)(Wp + (size_t)(k0 + kk) * 64 + c4 * 4);
            sB[w][c4 * 4 + 0][kk] = f2tf32(bv.x);
            sB[w][c4 * 4 + 1][kk] = f2tf32(bv.y);
            sB[w][c4 * 4 + 2][kk] = f2tf32(bv.z);
            sB[w][c4 * 4 + 3][kk] = f2tf32(bv.w);
        }
        __syncthreads();

#pragma unroll
        for (int s = 0; s < 4; s++) {    // source s pairs with mat s
            uint32_t af[2][4];
#pragma unroll
            for (int rt = 0; rt < 2; rt++) {
                int r = wy * 32 + rt * 16 + lr;
                af[rt][0] = sA[s][r][lc];
                af[rt][1] = sA[s][r + 8][lc];
                af[rt][2] = sA[s][r][lc + 4];
                af[rt][3] = sA[s][r + 8][lc + 4];
            }
            uint32_t bf[2][2];
#pragma unroll
            for (int ct = 0; ct < 2; ct++) {
                int c = wx * 16 + ct * 8 + lr;
                bf[ct][0] = sB[s][c][lc];
                bf[ct][1] = sB[s][c][lc + 4];
            }
#pragma unroll
            for (int rt = 0; rt < 2; rt++)
#pragma unroll
                for (int ct = 0; ct < 2; ct++)
                    mma_tf32(acc[rt][ct], af[rt], bf[ct]);
        }
        __syncthreads();
    }

#pragma unroll
    for (int rt = 0; rt < 2; rt++) {
#pragma unroll
        for (int ct = 0; ct < 2; ct++) {
            int c0 = wx * 16 + ct * 8 + lc * 2;
            float b0 = __ldg(&bias[c0])       + __ldg(&bias[64 + c0])
                     + __ldg(&bias[128 + c0]);
            float b1 = __ldg(&bias[c0 + 1])   + __ldg(&bias[64 + c0 + 1])
                     + __ldg(&bias[128 + c0 + 1]);
            int r0 = row0 + wy * 32 + rt * 16 + lr;
            if (r0 < N)
                *(float2*)(out + (size_t)r0 * DIM + c0) =
                    make_float2(acc[rt][ct][0] + b0, acc[rt][ct][1] + b1);
            if (r0 + 8 < N)
                *(float2*)(out + (size_t)(r0 + 8) * DIM + c0) =
                    make_float2(acc[rt][ct][2] + b0, acc[rt][ct][3] + b1);
        }
    }
}

// ---------------------------------------------------------------------------
// Launch
// ---------------------------------------------------------------------------
extern "C" void kernel_launch(void* const* d_in, const int* in_sizes, int n_in,
                              void* d_out, int out_size) {
    const float* feat    = (const float*)d_in[0];
    const float* W_self  = (const float*)d_in[1];
    const float* W_neigh = (const float*)d_in[2];
    const float* bias    = (const float*)d_in[3];
    const int*   src     = (const int*)d_in[4];
    const int*   dst     = (const int*)d_in[5];

    const int N = in_sizes[0] / DIM;       // 100000
    const int E = in_sizes[4] / NTYPES;    // 400000
    const int nseg = NTYPES * N;
    const int totE = NTYPES * E;
    float* out = (float*)d_out;

    void *ph, *pa, *pcsr, *poff, *pcur, *pbs, *pws;
    cudaGetSymbolAddress(&ph, g_h);
    cudaGetSymbolAddress(&pa, g_agg);
    cudaGetSymbolAddress(&pcsr, g_csr_src);
    cudaGetSymbolAddress(&poff, g_off);
    cudaGetSymbolAddress(&pcur, g_cur);
    cudaGetSymbolAddress(&pbs, g_bsums);
    cudaGetSymbolAddress(&pws, g_wsum);
    float* hbuf = (float*)ph;
    float* agg  = (float*)pa;
    int* csr    = (int*)pcsr;
    int* off    = (int*)poff;
    int* cur    = (int*)pcur;
    int* bsums  = (int*)pbs;
    float* wsum = (float*)pws;

    // ---- CSR build (graph constant across layers) ----
    {
        int n4 = (nseg + 3) / 4;
        zero_i4<<<(n4 + 255) / 256, 256>>>((int4*)cur, n4);
        hist_kernel<<<(totE + 255) / 256, 256>>>(dst, cur, E, N);
        int nb = (nseg + CHUNK - 1) / CHUNK;
        scan1_kernel<<<nb, 256>>>(cur, off, bsums, nseg);
        scan2_kernel<<<1, 128>>>(bsums, nb);
        scan3_kernel<<<(nseg + 255) / 256, 256>>>(off, cur, bsums, nseg, totE);
        fill_kernel<<<(totE + 255) / 256, 256>>>(src, dst, cur, csr, E, N);
        wsum_kernel<<<(DIM * DIM + 255) / 256, 256>>>(
            W_self + (size_t)(NLAYERS - 1) * NTYPES * DIM * DIM, wsum);
    }

    const int nblocks_gemm = (N + 63) / 64;
    const int agg_blocks = (int)(((long long)nseg * 16 + 255) / 256);

    const float* h_cur = feat;
    for (int l = 0; l < NLAYERS; l++) {
        agg_kernel<<<agg_blocks, 256>>>(h_cur, off, csr, agg, nseg);

        float* h_next = (l == NLAYERS - 1) ? out : hbuf + (size_t)(l & 1) * MAXN * DIM;
        const float* Ws = W_self  + (size_t)l * NTYPES * DIM * DIM;
        const float* Wn = W_neigh + (size_t)l * NTYPES * DIM * DIM;
        const float* bl = bias    + (size_t)l * NTYPES * DIM;

        if (l < NLAYERS - 1)
            layer_tc_kernel<<<nblocks_gemm, 256>>>(h_cur, agg, Ws, Wn, bl, h_next, N);
        else
            layer_last_tc_kernel<<<nblocks_gemm, 256>>>(h_cur, agg, wsum, Wn, bl, out, N);

        h_cur = h_next;
    }
}

// round 4
// speedup vs baseline: 2.6005x; 1.3196x over previous
#include <cuda_runtime.h>
#include <cstdint>

// Problem constants (hetero SAGEConv, 3 layers, 3 etypes)
#define DIM      64
#define NTYPES   3
#define NLAYERS  3
#define MAXN     100000
#define MAXE     400000
#define NSEG     (NTYPES * MAXN)
#define CHUNK    4096                 // scan chunk: 256 threads x 16 items
#define NMATS    16                   // 6+6 hidden + (wsum + 3 Wn) last

// Scratch: device globals (no runtime allocation allowed).
__device__ float g_h[2][(size_t)MAXN * DIM];           // ping-pong hidden states
__device__ float g_agg[(size_t)NTYPES * MAXN * DIM];   // per-etype mean aggregates
__device__ int   g_csr_src[(size_t)NTYPES * MAXE];     // src ids grouped by (etype,dst)
__device__ int   g_off[NSEG + 1];                      // segment offsets
__device__ int   g_cur[NSEG];                          // fill cursors
__device__ int   g_bsums[1024];                        // scan block sums
// Weight fragments, tf32, B-operand layout for mma.m16n8k8:
// [mat][kstep 0..7][colgroup 0..7][lane 0..31] as uint2
__device__ uint2 g_wfrag[(size_t)NMATS * 8 * 8 * 32];

// ---------------------------------------------------------------------------
// tf32 helpers
// ---------------------------------------------------------------------------
__device__ __forceinline__ uint32_t f2tf32(float f) {
    uint32_t u;
    asm("cvt.rna.tf32.f32 %0, %1;" : "=r"(u) : "f"(f));
    return u;
}

__device__ __forceinline__ void mma_tf32(float d[4], const uint32_t a[4],
                                         uint32_t b0, uint32_t b1) {
    asm volatile(
        "mma.sync.aligned.m16n8k8.row.col.f32.tf32.tf32.f32 "
        "{%0,%1,%2,%3}, {%4,%5,%6,%7}, {%8,%9}, {%0,%1,%2,%3};\n"
        : "+f"(d[0]), "+f"(d[1]), "+f"(d[2]), "+f"(d[3])
        : "r"(a[0]), "r"(a[1]), "r"(a[2]), "r"(a[3]), "r"(b0), "r"(b1));
}

// ---------------------------------------------------------------------------
// zero int4 region
// ---------------------------------------------------------------------------
__global__ void zero_i4(int4* __restrict__ p, int n4) {
    int i = blockIdx.x * blockDim.x + threadIdx.x;
    if (i < n4) p[i] = make_int4(0, 0, 0, 0);
}

// ---------------------------------------------------------------------------
// Weight prep: convert all matrices to tf32 in B-fragment layout.
// Slots: l*6+t = Ws[l,t], l*6+3+t = Wn[l,t] for l in {0,1};
//        12 = sum_t Ws[2,t]; 13..15 = Wn[2,t].
// ---------------------------------------------------------------------------
__global__ void prep_kernel(const float* __restrict__ Ws,
                            const float* __restrict__ Wn) {
    int idx = blockIdx.x * blockDim.x + threadIdx.x;
    if (idx >= NMATS * 2048) return;
    int m    = idx >> 11;
    int r    = idx & 2047;
    int ks   = r >> 8;             // 0..7
    int cg   = (r >> 5) & 7;       // 0..7
    int lane = r & 31;
    int col  = cg * 8 + (lane >> 2);
    int k    = ks * 8 + (lane & 3);

    float v0, v1;
    if (m < 12) {
        int l = m / 6, j = m % 6;
        const float* W = (j < 3) ? Ws + ((size_t)l * 3 + j) * 4096
                                 : Wn + ((size_t)l * 3 + (j - 3)) * 4096;
        v0 = W[k * 64 + col];
        v1 = W[(k + 4) * 64 + col];
    } else if (m == 12) {
        const float* W0 = Ws + (size_t)2 * 3 * 4096;
        v0 = W0[k * 64 + col] + W0[4096 + k * 64 + col] + W0[8192 + k * 64 + col];
        v1 = W0[(k + 4) * 64 + col] + W0[4096 + (k + 4) * 64 + col]
           + W0[8192 + (k + 4) * 64 + col];
    } else {
        const float* W = Wn + ((size_t)2 * 3 + (m - 13)) * 4096;
        v0 = W[k * 64 + col];
        v1 = W[(k + 4) * 64 + col];
    }
    g_wfrag[idx] = make_uint2(f2tf32(v0), f2tf32(v1));
}

// ---------------------------------------------------------------------------
// CSR build: histogram -> scan -> fill
// ---------------------------------------------------------------------------
__global__ void hist_kernel(const int* __restrict__ dst, int* __restrict__ cnt,
                            int E, int N) {
    int i = blockIdx.x * blockDim.x + threadIdx.x;
    if (i < NTYPES * E) {
        int t = i / E;
        atomicAdd(&cnt[t * N + dst[i]], 1);
    }
}

__global__ __launch_bounds__(256)
void scan1_kernel(const int* __restrict__ in, int* __restrict__ out,
                  int* __restrict__ bsums, int n) {
    __shared__ int sh[256];
    int b = blockIdx.x, t = threadIdx.x;
    int base = b * CHUNK + t * 16;
    int vals[16];
    int sum = 0;
#pragma unroll
    for (int i = 0; i < 16; i++) {
        int idx = base + i;
        int v = (idx < n) ? in[idx] : 0;
        vals[i] = sum;
        sum += v;
    }
    sh[t] = sum;
    __syncthreads();
    for (int off = 1; off < 256; off <<= 1) {
        int v = (t >= off) ? sh[t - off] : 0;
        __syncthreads();
        sh[t] += v;
        __syncthreads();
    }
    int texcl = (t == 0) ? 0 : sh[t - 1];
#pragma unroll
    for (int i = 0; i < 16; i++) {
        int idx = base + i;
        if (idx < n) out[idx] = vals[i] + texcl;
    }
    if (t == 255) bsums[b] = sh[255];
}

__global__ void scan2_kernel(int* __restrict__ bsums, int nb) {
    __shared__ int sh[128];
    int t = threadIdx.x;
    int v = (t < nb) ? bsums[t] : 0;
    sh[t] = v;
    __syncthreads();
    for (int off = 1; off < 128; off <<= 1) {
        int u = (t >= off) ? sh[t - off] : 0;
        __syncthreads();
        sh[t] += u;
        __syncthreads();
    }
    if (t < nb) bsums[t] = sh[t] - v;
}

__global__ void scan3_kernel(int* __restrict__ off, int* __restrict__ cur,
                             const int* __restrict__ bsums, int n, int total) {
    int i = blockIdx.x * blockDim.x + threadIdx.x;
    if (i < n) {
        int v = off[i] + bsums[i / CHUNK];
        off[i] = v;
        cur[i] = v;
    }
    if (i == 0) off[n] = total;
}

__global__ void fill_kernel(const int* __restrict__ src, const int* __restrict__ dst,
                            int* __restrict__ cur, int* __restrict__ csr,
                            int E, int N) {
    int i = blockIdx.x * blockDim.x + threadIdx.x;
    if (i < NTYPES * E) {
        int t = i / E;
        int pos = atomicAdd(&cur[t * N + dst[i]], 1);
        csr[pos] = src[i];
    }
}

// ---------------------------------------------------------------------------
// Gather-mean aggregation: 16 lanes per (etype,node) segment, float4 per lane.
// csr prefetch pipelined past the dependent h-row load.
// ---------------------------------------------------------------------------
__global__ __launch_bounds__(256)
void agg_kernel(const float* __restrict__ h, const int* __restrict__ off,
                const int* __restrict__ csr, float* __restrict__ agg, int nseg) {
    long long gid = (long long)blockIdx.x * blockDim.x + threadIdx.x;
    int seg = (int)(gid >> 4);
    if (seg >= nseg) return;
    int lane = (int)(gid & 15);
    int b = __ldg(&off[seg]);
    int e = __ldg(&off[seg + 1]);
    float4 acc = make_float4(0.f, 0.f, 0.f, 0.f);
    if (b < e) {
        int s_next = __ldg(&csr[b]);
        for (int i = b; i < e; i++) {
            int s = s_next;
            if (i + 1 < e) s_next = __ldg(&csr[i + 1]);
            float4 v = *(const float4*)(h + (size_t)s * DIM + lane * 4);
            acc.x += v.x; acc.y += v.y; acc.z += v.z; acc.w += v.w;
        }
        float w = 1.0f / (float)(e - b);
        acc.x *= w; acc.y *= w; acc.z *= w; acc.w *= w;
    }
    *(float4*)(agg + (size_t)seg * DIM + lane * 4) = acc;
}

// ---------------------------------------------------------------------------
// Hidden layer (tf32 mma, B fragments direct from global/L1):
//   out[n] = sum_t relu( h[n] @ Ws_t + mean_t[n] @ Wn_t + b_t )
// 256 threads (8 warps, 2x4), tile 64x64. Warp: 32 rows x 16 cols, all 3 rels.
// ---------------------------------------------------------------------------
__global__ __launch_bounds__(256, 2)
void layer_tc_kernel(const float* __restrict__ h,
                     const float* __restrict__ agg,   // [3][N*64]
                     const float* __restrict__ bias,  // [3][64]
                     float* __restrict__ out,
                     int N, int slot0) {
    __shared__ uint32_t sA[4][64][8];   // [src][row][kk]  8 KB

    const int tid = threadIdx.x;
    const int lane = tid & 31;
    const int warp = tid >> 5;
    const int wy = warp >> 2;      // 0..1
    const int wx = warp & 3;       // 0..3
    const int lr = lane >> 2;      // 0..7
    const int lc = lane & 3;       // 0..3
    const int row0 = blockIdx.x * 64;

    float acc[3][2][2][4];
#pragma unroll
    for (int t = 0; t < 3; t++)
#pragma unroll
        for (int rt = 0; rt < 2; rt++)
#pragma unroll
            for (int ct = 0; ct < 2; ct++)
#pragma unroll
                for (int q = 0; q < 4; q++) acc[t][rt][ct][q] = 0.f;

    const int s_src = tid >> 6;
    const int r_src = tid & 63;
    const int row_g = row0 + r_src;
    const bool rowok = row_g < N;
    const float* srcp = (s_src == 0)
        ? h + (size_t)row_g * DIM
        : agg + ((size_t)(s_src - 1) * N + row_g) * DIM;

    // per-warp B fragment base: lane-indexed uint2 rows of g_wfrag
    const uint2* fragbase = g_wfrag + lane;

    for (int ks = 0; ks < 8; ks++) {
        const int k0 = ks * 8;
        // ---- stage A: vectorized cvt + STS.128 ----
        float4 v0 = rowok ? *(const float4*)(srcp + k0)
                          : make_float4(0.f, 0.f, 0.f, 0.f);
        float4 v1 = rowok ? *(const float4*)(srcp + k0 + 4)
                          : make_float4(0.f, 0.f, 0.f, 0.f);
        uint4 u0 = make_uint4(f2tf32(v0.x), f2tf32(v0.y), f2tf32(v0.z), f2tf32(v0.w));
        uint4 u1 = make_uint4(f2tf32(v1.x), f2tf32(v1.y), f2tf32(v1.z), f2tf32(v1.w));
        uint4* dstp = (uint4*)&sA[s_src][r_src][0];
        dstp[0] = u0;
        dstp[1] = u1;
        __syncthreads();

        // ---- A fragments for h ----
        uint32_t ah[2][4];
#pragma unroll
        for (int rt = 0; rt < 2; rt++) {
            int r = wy * 32 + rt * 16 + lr;
            ah[rt][0] = sA[0][r][lc];
            ah[rt][1] = sA[0][r + 8][lc];
            ah[rt][2] = sA[0][r][lc + 4];
            ah[rt][3] = sA[0][r + 8][lc + 4];
        }

#pragma unroll
        for (int t = 0; t < 3; t++) {
            // self weights (slot0+t)
            uint2 bs[2];
#pragma unroll
            for (int ct = 0; ct < 2; ct++)
                bs[ct] = __ldg(&fragbase[(((size_t)(slot0 + t) * 8 + ks) * 8
                                          + (wx * 2 + ct)) * 32]);
#pragma unroll
            for (int rt = 0; rt < 2; rt++)
#pragma unroll
                for (int ct = 0; ct < 2; ct++)
                    mma_tf32(acc[t][rt][ct], ah[rt], bs[ct].x, bs[ct].y);

            // neighbor weights (slot0+3+t) with mean_t
            uint32_t am[2][4];
#pragma unroll
            for (int rt = 0; rt < 2; rt++) {
                int r = wy * 32 + rt * 16 + lr;
                am[rt][0] = sA[1 + t][r][lc];
                am[rt][1] = sA[1 + t][r + 8][lc];
                am[rt][2] = sA[1 + t][r][lc + 4];
                am[rt][3] = sA[1 + t][r + 8][lc + 4];
            }
            uint2 bn[2];
#pragma unroll
            for (int ct = 0; ct < 2; ct++)
                bn[ct] = __ldg(&fragbase[(((size_t)(slot0 + 3 + t) * 8 + ks) * 8
                                          + (wx * 2 + ct)) * 32]);
#pragma unroll
            for (int rt = 0; rt < 2; rt++)
#pragma unroll
                for (int ct = 0; ct < 2; ct++)
                    mma_tf32(acc[t][rt][ct], am[rt], bn[ct].x, bn[ct].y);
        }
        __syncthreads();
    }

    // ---- epilogue: bias + relu per relation, sum, store ----
#pragma unroll
    for (int rt = 0; rt < 2; rt++) {
#pragma unroll
        for (int ct = 0; ct < 2; ct++) {
            int c0 = wx * 16 + ct * 8 + lc * 2;
            float ov[4] = {0.f, 0.f, 0.f, 0.f};
#pragma unroll
            for (int t = 0; t < 3; t++) {
                float b0 = __ldg(&bias[t * 64 + c0]);
                float b1 = __ldg(&bias[t * 64 + c0 + 1]);
                ov[0] += fmaxf(acc[t][rt][ct][0] + b0, 0.f);
                ov[1] += fmaxf(acc[t][rt][ct][1] + b1, 0.f);
                ov[2] += fmaxf(acc[t][rt][ct][2] + b0, 0.f);
                ov[3] += fmaxf(acc[t][rt][ct][3] + b1, 0.f);
            }
            int r0 = row0 + wy * 32 + rt * 16 + lr;
            if (r0 < N)
                *(float2*)(out + (size_t)r0 * DIM + c0) = make_float2(ov[0], ov[1]);
            if (r0 + 8 < N)
                *(float2*)(out + (size_t)(r0 + 8) * DIM + c0) = make_float2(ov[2], ov[3]);
        }
    }
}

// ---------------------------------------------------------------------------
// Last layer (no ReLU): out = h @ Wsum + sum_t mean_t @ Wn_t + sum_t b_t
// Slots: 12 (wsum, pairs with h), 13..15 (Wn, pair with mean_t).
// ---------------------------------------------------------------------------
__global__ __launch_bounds__(256, 2)
void layer_last_tc_kernel(const float* __restrict__ h,
                          const float* __restrict__ agg,
                          const float* __restrict__ bias,  // [3][64]
                          float* __restrict__ out,
                          int N) {
    __shared__ uint32_t sA[4][64][8];

    const int tid = threadIdx.x;
    const int lane = tid & 31;
    const int warp = tid >> 5;
    const int wy = warp >> 2;
    const int wx = warp & 3;
    const int lr = lane >> 2;
    const int lc = lane & 3;
    const int row0 = blockIdx.x * 64;

    float acc[2][2][4];
#pragma unroll
    for (int rt = 0; rt < 2; rt++)
#pragma unroll
        for (int ct = 0; ct < 2; ct++)
#pragma unroll
            for (int q = 0; q < 4; q++) acc[rt][ct][q] = 0.f;

    const int s_src = tid >> 6;
    const int r_src = tid & 63;
    const int row_g = row0 + r_src;
    const bool rowok = row_g < N;
    const float* srcp = (s_src == 0)
        ? h + (size_t)row_g * DIM
        : agg + ((size_t)(s_src - 1) * N + row_g) * DIM;

    const uint2* fragbase = g_wfrag + lane;

    for (int ks = 0; ks < 8; ks++) {
        const int k0 = ks * 8;
        float4 v0 = rowok ? *(const float4*)(srcp + k0)
                          : make_float4(0.f, 0.f, 0.f, 0.f);
        float4 v1 = rowok ? *(const float4*)(srcp + k0 + 4)
                          : make_float4(0.f, 0.f, 0.f, 0.f);
        uint4 u0 = make_uint4(f2tf32(v0.x), f2tf32(v0.y), f2tf32(v0.z), f2tf32(v0.w));
        uint4 u1 = make_uint4(f2tf32(v1.x), f2tf32(v1.y), f2tf32(v1.z), f2tf32(v1.w));
        uint4* dstp = (uint4*)&sA[s_src][r_src][0];
        dstp[0] = u0;
        dstp[1] = u1;
        __syncthreads();

#pragma unroll
        for (int s = 0; s < 4; s++) {
            uint32_t af[2][4];
#pragma unroll
            for (int rt = 0; rt < 2; rt++) {
                int r = wy * 32 + rt * 16 + lr;
                af[rt][0] = sA[s][r][lc];
                af[rt][1] = sA[s][r + 8][lc];
                af[rt][2] = sA[s][r][lc + 4];
                af[rt][3] = sA[s][r + 8][lc + 4];
            }
            uint2 bf[2];
#pragma unroll
            for (int ct = 0; ct < 2; ct++)
                bf[ct] = __ldg(&fragbase[(((size_t)(12 + s) * 8 + ks) * 8
                                          + (wx * 2 + ct)) * 32]);
#pragma unroll
            for (int rt = 0; rt < 2; rt++)
#pragma unroll
                for (int ct = 0; ct < 2; ct++)
                    mma_tf32(acc[rt][ct], af[rt], bf[ct].x, bf[ct].y);
        }
        __syncthreads();
    }

#pragma unroll
    for (int rt = 0; rt < 2; rt++) {
#pragma unroll
        for (int ct = 0; ct < 2; ct++) {
            int c0 = wx * 16 + ct * 8 + lc * 2;
            float b0 = __ldg(&bias[c0])     + __ldg(&bias[64 + c0])
                     + __ldg(&bias[128 + c0]);
            float b1 = __ldg(&bias[c0 + 1]) + __ldg(&bias[64 + c0 + 1])
                     + __ldg(&bias[128 + c0 + 1]);
            int r0 = row0 + wy * 32 + rt * 16 + lr;
            if (r0 < N)
                *(float2*)(out + (size_t)r0 * DIM + c0) =
                    make_float2(acc[rt][ct][0] + b0, acc[rt][ct][1] + b1);
            if (r0 + 8 < N)
                *(float2*)(out + (size_t)(r0 + 8) * DIM + c0) =
                    make_float2(acc[rt][ct][2] + b0, acc[rt][ct][3] + b1);
        }
    }
}

// ---------------------------------------------------------------------------
// Launch
// ---------------------------------------------------------------------------
extern "C" void kernel_launch(void* const* d_in, const int* in_sizes, int n_in,
                              void* d_out, int out_size) {
    const float* feat    = (const float*)d_in[0];
    const float* W_self  = (const float*)d_in[1];
    const float* W_neigh = (const float*)d_in[2];
    const float* bias    = (const float*)d_in[3];
    const int*   src     = (const int*)d_in[4];
    const int*   dst     = (const int*)d_in[5];

    const int N = in_sizes[0] / DIM;       // 100000
    const int E = in_sizes[4] / NTYPES;    // 400000
    const int nseg = NTYPES * N;
    const int totE = NTYPES * E;
    float* out = (float*)d_out;

    void *ph, *pa, *pcsr, *poff, *pcur, *pbs;
    cudaGetSymbolAddress(&ph, g_h);
    cudaGetSymbolAddress(&pa, g_agg);
    cudaGetSymbolAddress(&pcsr, g_csr_src);
    cudaGetSymbolAddress(&poff, g_off);
    cudaGetSymbolAddress(&pcur, g_cur);
    cudaGetSymbolAddress(&pbs, g_bsums);
    float* hbuf = (float*)ph;
    float* agg  = (float*)pa;
    int* csr    = (int*)pcsr;
    int* off    = (int*)poff;
    int* cur    = (int*)pcur;
    int* bsums  = (int*)pbs;

    // ---- CSR build + weight prep (graph/weights constant across layers) ----
    {
        int n4 = (nseg + 3) / 4;
        zero_i4<<<(n4 + 255) / 256, 256>>>((int4*)cur, n4);
        hist_kernel<<<(totE + 255) / 256, 256>>>(dst, cur, E, N);
        int nb = (nseg + CHUNK - 1) / CHUNK;
        scan1_kernel<<<nb, 256>>>(cur, off, bsums, nseg);
        scan2_kernel<<<1, 128>>>(bsums, nb);
        scan3_kernel<<<(nseg + 255) / 256, 256>>>(off, cur, bsums, nseg, totE);
        fill_kernel<<<(totE + 255) / 256, 256>>>(src, dst, cur, csr, E, N);
        prep_kernel<<<(NMATS * 2048 + 255) / 256, 256>>>(W_self, W_neigh);
    }

    const int nblocks_gemm = (N + 63) / 64;
    const int agg_blocks = (int)(((long long)nseg * 16 + 255) / 256);

    const float* h_cur = feat;
    for (int l = 0; l < NLAYERS; l++) {
        agg_kernel<<<agg_blocks, 256>>>(h_cur, off, csr, agg, nseg);

        float* h_next = (l == NLAYERS - 1) ? out : hbuf + (size_t)(l & 1) * MAXN * DIM;
        const float* bl = bias + (size_t)l * NTYPES * DIM;

        if (l < NLAYERS - 1)
            layer_tc_kernel<<<nblocks_gemm, 256>>>(h_cur, agg, bl, h_next, N, l * 6);
        else
            layer_last_tc_kernel<<<nblocks_gemm, 256>>>(h_cur, agg, bl, out, N);

        h_cur = h_next;
    }
}

// round 5
// speedup vs baseline: 5.5048x; 2.1168x over previous
#include <cuda_runtime.h>
#include <cuda_fp16.h>
#include <cstdint>

// Problem constants (hetero SAGEConv, 3 layers, 3 etypes)
#define DIM      64
#define NTYPES   3
#define NLAYERS  3
#define MAXN     100000
#define MAXE     400000
#define NSEG     (NTYPES * MAXN)
#define CHUNK    4096                 // scan chunk: 256 threads x 16 items
#define NMATS    16                   // 6+6 hidden + (wsum + 3 Wn) last

// Scratch: device globals (no runtime allocation allowed).
__device__ __half g_hh[2][(size_t)MAXN * DIM];          // ping-pong hidden (fp16)
__device__ __half g_aggh[(size_t)NTYPES * MAXN * DIM];  // per-etype means (fp16)
__device__ int    g_csr_src[(size_t)NTYPES * MAXE];     // src ids grouped by (etype,dst)
__device__ int    g_off[NSEG + 1];
__device__ int    g_cur[NSEG];
__device__ int    g_bsums[1024];
// Weight fragments, fp16, B-operand layout for mma.m16n8k16:
// [mat][kstep 0..3][colgroup 0..7][lane 0..31] as uint2 (two half2)
__device__ uint2  g_wfrag[(size_t)NMATS * 4 * 8 * 32];

// ---------------------------------------------------------------------------
// helpers
// ---------------------------------------------------------------------------
__device__ __forceinline__ uint32_t pack_h2(float a, float b) {
    __half2 h = __floats2half2_rn(a, b);
    return *reinterpret_cast<uint32_t*>(&h);
}

__device__ __forceinline__ void mma_f16(float d[4], const uint32_t a[4],
                                        uint32_t b0, uint32_t b1) {
    asm volatile(
        "mma.sync.aligned.m16n8k16.row.col.f32.f16.f16.f32 "
        "{%0,%1,%2,%3}, {%4,%5,%6,%7}, {%8,%9}, {%0,%1,%2,%3};\n"
        : "+f"(d[0]), "+f"(d[1]), "+f"(d[2]), "+f"(d[3])
        : "r"(a[0]), "r"(a[1]), "r"(a[2]), "r"(a[3]), "r"(b0), "r"(b1));
}

__device__ __forceinline__ void ldsm_x4(uint32_t a[4], uint32_t addr) {
    asm volatile("ldmatrix.sync.aligned.m8n8.x4.shared.b16 {%0,%1,%2,%3}, [%4];"
                 : "=r"(a[0]), "=r"(a[1]), "=r"(a[2]), "=r"(a[3]) : "r"(addr));
}

// ---------------------------------------------------------------------------
// zero int4 region
// ---------------------------------------------------------------------------
__global__ void zero_i4(int4* __restrict__ p, int n4) {
    int i = blockIdx.x * blockDim.x + threadIdx.x;
    if (i < n4) p[i] = make_int4(0, 0, 0, 0);
}

// ---------------------------------------------------------------------------
// feat (fp32) -> fp16
// ---------------------------------------------------------------------------
__global__ void f2h_kernel(const float4* __restrict__ in, uint2* __restrict__ out,
                           int n4) {
    int i = blockIdx.x * blockDim.x + threadIdx.x;
    if (i < n4) {
        float4 v = in[i];
        out[i] = make_uint2(pack_h2(v.x, v.y), pack_h2(v.z, v.w));
    }
}

// ---------------------------------------------------------------------------
// Weight prep: all matrices -> fp16 B-fragment layout (m16n8k16).
// Slots: l*6+t = Ws[l,t], l*6+3+t = Wn[l,t] for l in {0,1};
//        12 = sum_t Ws[2,t]; 13..15 = Wn[2,t].
// frag[(mat*4+ks)*8+cg][lane]: lo=(B[k0+2lc],B[k0+2lc+1]); hi=(+8,+9); col=cg*8+lane/4
// ---------------------------------------------------------------------------
__global__ void prep_kernel(const float* __restrict__ Ws,
                            const float* __restrict__ Wn) {
    int idx = blockIdx.x * blockDim.x + threadIdx.x;
    if (idx >= NMATS * 1024) return;
    int m    = idx >> 10;
    int r    = idx & 1023;
    int ks   = r >> 8;             // 0..3
    int cg   = (r >> 5) & 7;       // 0..7
    int lane = r & 31;
    int col  = cg * 8 + (lane >> 2);
    int kb   = ks * 16 + (lane & 3) * 2;

    float w[4];
    if (m < 12) {
        int l = m / 6, j = m % 6;
        const float* W = (j < 3) ? Ws + ((size_t)l * 3 + j) * 4096
                                 : Wn + ((size_t)l * 3 + (j - 3)) * 4096;
        w[0] = W[kb * 64 + col];       w[1] = W[(kb + 1) * 64 + col];
        w[2] = W[(kb + 8) * 64 + col]; w[3] = W[(kb + 9) * 64 + col];
    } else if (m == 12) {
        const float* W0 = Ws + (size_t)2 * 3 * 4096;
#pragma unroll
        for (int q = 0; q < 4; q++) {
            int k = kb + (q & 1) + (q >> 1) * 8;
            w[q] = W0[k * 64 + col] + W0[4096 + k * 64 + col] + W0[8192 + k * 64 + col];
        }
    } else {
        const float* W = Wn + ((size_t)2 * 3 + (m - 13)) * 4096;
        w[0] = W[kb * 64 + col];       w[1] = W[(kb + 1) * 64 + col];
        w[2] = W[(kb + 8) * 64 + col]; w[3] = W[(kb + 9) * 64 + col];
    }
    g_wfrag[idx] = make_uint2(pack_h2(w[0], w[1]), pack_h2(w[2], w[3]));
}

// ---------------------------------------------------------------------------
// CSR build: histogram -> scan -> fill
// ---------------------------------------------------------------------------
__global__ void hist_kernel(const int* __restrict__ dst, int* __restrict__ cnt,
                            int E, int N) {
    int i = blockIdx.x * blockDim.x + threadIdx.x;
    if (i < NTYPES * E) {
        int t = i / E;
        atomicAdd(&cnt[t * N + dst[i]], 1);
    }
}

__global__ __launch_bounds__(256)
void scan1_kernel(const int* __restrict__ in, int* __restrict__ out,
                  int* __restrict__ bsums, int n) {
    __shared__ int sh[256];
    int b = blockIdx.x, t = threadIdx.x;
    int base = b * CHUNK + t * 16;
    int vals[16];
    int sum = 0;
#pragma unroll
    for (int i = 0; i < 16; i++) {
        int idx = base + i;
        int v = (idx < n) ? in[idx] : 0;
        vals[i] = sum;
        sum += v;
    }
    sh[t] = sum;
    __syncthreads();
    for (int off = 1; off < 256; off <<= 1) {
        int v = (t >= off) ? sh[t - off] : 0;
        __syncthreads();
        sh[t] += v;
        __syncthreads();
    }
    int texcl = (t == 0) ? 0 : sh[t - 1];
#pragma unroll
    for (int i = 0; i < 16; i++) {
        int idx = base + i;
        if (idx < n) out[idx] = vals[i] + texcl;
    }
    if (t == 255) bsums[b] = sh[255];
}

__global__ void scan2_kernel(int* __restrict__ bsums, int nb) {
    __shared__ int sh[128];
    int t = threadIdx.x;
    int v = (t < nb) ? bsums[t] : 0;
    sh[t] = v;
    __syncthreads();
    for (int off = 1; off < 128; off <<= 1) {
        int u = (t >= off) ? sh[t - off] : 0;
        __syncthreads();
        sh[t] += u;
        __syncthreads();
    }
    if (t < nb) bsums[t] = sh[t] - v;
}

__global__ void scan3_kernel(int* __restrict__ off, int* __restrict__ cur,
                             const int* __restrict__ bsums, int n, int total) {
    int i = blockIdx.x * blockDim.x + threadIdx.x;
    if (i < n) {
        int v = off[i] + bsums[i / CHUNK];
        off[i] = v;
        cur[i] = v;
    }
    if (i == 0) off[n] = total;
}

__global__ void fill_kernel(const int* __restrict__ src, const int* __restrict__ dst,
                            int* __restrict__ cur, int* __restrict__ csr,
                            int E, int N) {
    int i = blockIdx.x * blockDim.x + threadIdx.x;
    if (i < NTYPES * E) {
        int t = i / E;
        int pos = atomicAdd(&cur[t * N + dst[i]], 1);
        csr[pos] = src[i];
    }
}

// ---------------------------------------------------------------------------
// Gather-mean aggregation (fp16 h): 8 lanes per segment, 8 dims per lane
// (one uint4 = 8 fp16). fp32 accumulation, fp16 output.
// ---------------------------------------------------------------------------
__global__ __launch_bounds__(256)
void agg_kernel(const __half* __restrict__ h, const int* __restrict__ off,
                const int* __restrict__ csr, __half* __restrict__ aggh, int nseg) {
    long long gid = (long long)blockIdx.x * blockDim.x + threadIdx.x;
    int seg = (int)(gid >> 3);
    if (seg >= nseg) return;
    int lane = (int)(gid & 7);
    int b = __ldg(&off[seg]);
    int e = __ldg(&off[seg + 1]);
    float acc[8] = {0.f, 0.f, 0.f, 0.f, 0.f, 0.f, 0.f, 0.f};
    if (b < e) {
        int s_next = __ldg(&csr[b]);
        for (int i = b; i < e; i++) {
            int s = s_next;
            if (i + 1 < e) s_next = __ldg(&csr[i + 1]);
            uint4 v = *(const uint4*)(h + (size_t)s * DIM + lane * 8);
            const __half2* hp = reinterpret_cast<const __half2*>(&v);
#pragma unroll
            for (int j = 0; j < 4; j++) {
                float2 f = __half22float2(hp[j]);
                acc[j * 2]     += f.x;
                acc[j * 2 + 1] += f.y;
            }
        }
        float w = 1.0f / (float)(e - b);
#pragma unroll
        for (int j = 0; j < 8; j++) acc[j] *= w;
    }
    uint4 o;
    o.x = pack_h2(acc[0], acc[1]);
    o.y = pack_h2(acc[2], acc[3]);
    o.z = pack_h2(acc[4], acc[5]);
    o.w = pack_h2(acc[6], acc[7]);
    *(uint4*)(aggh + (size_t)seg * DIM + lane * 8) = o;
}

// ---------------------------------------------------------------------------
// Hidden layer, fp16 MMA (m16n8k16, fp32 accum):
//   out[n] = sum_t relu( h[n] @ Ws_t + mean_t[n] @ Wn_t + b_t )   (fp16 out)
// 256 threads (8 warps, 2x4), tile 64 rows x 64 cols. Whole A tile (4 sources,
// XOR-swizzled fp16) staged once; sync-free k-loop with ldmatrix fragments.
// ---------------------------------------------------------------------------
__global__ __launch_bounds__(256, 2)
void layer_fp16_kernel(const __half* __restrict__ h,
                       const __half* __restrict__ aggh,  // [3][N*64]
                       const float* __restrict__ bias,   // [3][64]
                       __half* __restrict__ out,
                       int N, int slot0) {
    __shared__ uint4 sA[4 * 64 * 8];   // [src][row][unit], unit swizzled; 32 KB

    const int tid = threadIdx.x;
    const int lane = tid & 31;
    const int warp = tid >> 5;
    const int wy = warp >> 2;      // 0..1
    const int wx = warp & 3;       // 0..3
    const int lr = lane >> 2;      // 0..7
    const int lc = lane & 3;       // 0..3
    const int row0 = blockIdx.x * 64;

    // ---- stage full A tile: 4 src x 64 rows x 8 uint4 ----
#pragma unroll
    for (int p = 0; p < 8; p++) {
        int f = p * 256 + tid;         // 0..2047
        int src = f >> 9;
        int rem = f & 511;
        int row = rem >> 3;
        int unit = rem & 7;
        int rowg = row0 + row;
        uint4 v = make_uint4(0u, 0u, 0u, 0u);
        if (rowg < N) {
            const uint4* gp = (src == 0)
                ? (const uint4*)(h + (size_t)rowg * DIM)
                : (const uint4*)(aggh + ((size_t)(src - 1) * N + rowg) * DIM);
            v = __ldg(&gp[unit]);
        }
        sA[(src * 64 + row) * 8 + (unit ^ (row & 7))] = v;
    }
    __syncthreads();

    float acc[3][2][2][4];
#pragma unroll
    for (int t = 0; t < 3; t++)
#pragma unroll
        for (int rt = 0; rt < 2; rt++)
#pragma unroll
            for (int ct = 0; ct < 2; ct++)
#pragma unroll
                for (int q = 0; q < 4; q++) acc[t][rt][ct][q] = 0.f;

    uint32_t sbase = (uint32_t)__cvta_generic_to_shared(sA);
    const int lrow  = (lane & 7) + ((lane >> 3) & 1) * 8;  // ldmatrix row id
    const int khalf = lane >> 4;                            // 0/1: k-lo/k-hi 16B unit
    const uint2* fragbase = g_wfrag + lane;

#pragma unroll
    for (int ks = 0; ks < 4; ks++) {
        // B fragments: 6 mats x 2 col-groups (LDG.64, L1-resident)
        uint2 bf[6][2];
#pragma unroll
        for (int m = 0; m < 6; m++)
#pragma unroll
            for (int ct = 0; ct < 2; ct++)
                bf[m][ct] = __ldg(&fragbase[(((size_t)(slot0 + m) * 4 + ks) * 8
                                             + (wx * 2 + ct)) * 32]);

#pragma unroll
        for (int srcm = 0; srcm < 4; srcm++) {
            uint32_t a[2][4];
#pragma unroll
            for (int rt = 0; rt < 2; rt++) {
                int row = wy * 32 + rt * 16 + lrow;
                int unit = (ks * 2 + khalf) ^ (row & 7);
                uint32_t addr = sbase + (((srcm * 64 + row) * 8 + unit) << 4);
                ldsm_x4(a[rt], addr);
            }
            if (srcm == 0) {
#pragma unroll
                for (int t = 0; t < 3; t++)
#pragma unroll
                    for (int rt = 0; rt < 2; rt++)
#pragma unroll
                        for (int ct = 0; ct < 2; ct++)
                            mma_f16(acc[t][rt][ct], a[rt], bf[t][ct].x, bf[t][ct].y);
            } else {
                int t = srcm - 1;
#pragma unroll
                for (int rt = 0; rt < 2; rt++)
#pragma unroll
                    for (int ct = 0; ct < 2; ct++)
                        mma_f16(acc[t][rt][ct], a[rt], bf[3 + t][ct].x, bf[3 + t][ct].y);
            }
        }
    }

    // ---- epilogue: bias + relu per relation, sum, fp16 store ----
#pragma unroll
    for (int rt = 0; rt < 2; rt++) {
#pragma unroll
        for (int ct = 0; ct < 2; ct++) {
            int c0 = wx * 16 + ct * 8 + lc * 2;
            float ov[4] = {0.f, 0.f, 0.f, 0.f};
#pragma unroll
            for (int t = 0; t < 3; t++) {
                float b0 = __ldg(&bias[t * 64 + c0]);
                float b1 = __ldg(&bias[t * 64 + c0 + 1]);
                ov[0] += fmaxf(acc[t][rt][ct][0] + b0, 0.f);
                ov[1] += fmaxf(acc[t][rt][ct][1] + b1, 0.f);
                ov[2] += fmaxf(acc[t][rt][ct][2] + b0, 0.f);
                ov[3] += fmaxf(acc[t][rt][ct][3] + b1, 0.f);
            }
            int r0 = row0 + wy * 32 + rt * 16 + lr;
            if (r0 < N)
                *reinterpret_cast<uint32_t*>(out + (size_t)r0 * DIM + c0) =
                    pack_h2(ov[0], ov[1]);
            if (r0 + 8 < N)
                *reinterpret_cast<uint32_t*>(out + (size_t)(r0 + 8) * DIM + c0) =
                    pack_h2(ov[2], ov[3]);
        }
    }
}

// ---------------------------------------------------------------------------
// Last layer (no ReLU, fp32 out): out = h@Wsum + sum_t mean_t@Wn_t + sum_t b_t
// Slots: 12 (wsum, pairs with h), 13..15 (Wn_t, pairs with mean_t).
// ---------------------------------------------------------------------------
__global__ __launch_bounds__(256, 2)
void layer_last_fp16_kernel(const __half* __restrict__ h,
                            const __half* __restrict__ aggh,
                            const float* __restrict__ bias,  // [3][64]
                            float* __restrict__ out,
                            int N) {
    __shared__ uint4 sA[4 * 64 * 8];

    const int tid = threadIdx.x;
    const int lane = tid & 31;
    const int warp = tid >> 5;
    const int wy = warp >> 2;
    const int wx = warp & 3;
    const int lr = lane >> 2;
    const int lc = lane & 3;
    const int row0 = blockIdx.x * 64;

#pragma unroll
    for (int p = 0; p < 8; p++) {
        int f = p * 256 + tid;
        int src = f >> 9;
        int rem = f & 511;
        int row = rem >> 3;
        int unit = rem & 7;
        int rowg = row0 + row;
        uint4 v = make_uint4(0u, 0u, 0u, 0u);
        if (rowg < N) {
            const uint4* gp = (src == 0)
                ? (const uint4*)(h + (size_t)rowg * DIM)
                : (const uint4*)(aggh + ((size_t)(src - 1) * N + rowg) * DIM);
            v = __ldg(&gp[unit]);
        }
        sA[(src * 64 + row) * 8 + (unit ^ (row & 7))] = v;
    }
    __syncthreads();

    float acc[2][2][4];
#pragma unroll
    for (int rt = 0; rt < 2; rt++)
#pragma unroll
        for (int ct = 0; ct < 2; ct++)
#pragma unroll
            for (int q = 0; q < 4; q++) acc[rt][ct][q] = 0.f;

    uint32_t sbase = (uint32_t)__cvta_generic_to_shared(sA);
    const int lrow  = (lane & 7) + ((lane >> 3) & 1) * 8;
    const int khalf = lane >> 4;
    const uint2* fragbase = g_wfrag + lane;

#pragma unroll
    for (int ks = 0; ks < 4; ks++) {
#pragma unroll
        for (int srcm = 0; srcm < 4; srcm++) {
            uint2 bf[2];
#pragma unroll
            for (int ct = 0; ct < 2; ct++)
                bf[ct] = __ldg(&fragbase[(((size_t)(12 + srcm) * 4 + ks) * 8
                                          + (wx * 2 + ct)) * 32]);
            uint32_t a[2][4];
#pragma unroll
            for (int rt = 0; rt < 2; rt++) {
                int row = wy * 32 + rt * 16 + lrow;
                int unit = (ks * 2 + khalf) ^ (row & 7);
                uint32_t addr = sbase + (((srcm * 64 + row) * 8 + unit) << 4);
                ldsm_x4(a[rt], addr);
            }
#pragma unroll
            for (int rt = 0; rt < 2; rt++)
#pragma unroll
                for (int ct = 0; ct < 2; ct++)
                    mma_f16(acc[rt][ct], a[rt], bf[ct].x, bf[ct].y);
        }
    }

#pragma unroll
    for (int rt = 0; rt < 2; rt++) {
#pragma unroll
        for (int ct = 0; ct < 2; ct++) {
            int c0 = wx * 16 + ct * 8 + lc * 2;
            float b0 = __ldg(&bias[c0])     + __ldg(&bias[64 + c0])
                     + __ldg(&bias[128 + c0]);
            float b1 = __ldg(&bias[c0 + 1]) + __ldg(&bias[64 + c0 + 1])
                     + __ldg(&bias[128 + c0 + 1]);
            int r0 = row0 + wy * 32 + rt * 16 + lr;
            if (r0 < N)
                *(float2*)(out + (size_t)r0 * DIM + c0) =
                    make_float2(acc[rt][ct][0] + b0, acc[rt][ct][1] + b1);
            if (r0 + 8 < N)
                *(float2*)(out + (size_t)(r0 + 8) * DIM + c0) =
                    make_float2(acc[rt][ct][2] + b0, acc[rt][ct][3] + b1);
        }
    }
}

// ---------------------------------------------------------------------------
// Launch
// ---------------------------------------------------------------------------
extern "C" void kernel_launch(void* const* d_in, const int* in_sizes, int n_in,
                              void* d_out, int out_size) {
    const float* feat    = (const float*)d_in[0];
    const float* W_self  = (const float*)d_in[1];
    const float* W_neigh = (const float*)d_in[2];
    const float* bias    = (const float*)d_in[3];
    const int*   src     = (const int*)d_in[4];
    const int*   dst     = (const int*)d_in[5];

    const int N = in_sizes[0] / DIM;       // 100000
    const int E = in_sizes[4] / NTYPES;    // 400000
    const int nseg = NTYPES * N;
    const int totE = NTYPES * E;
    float* out = (float*)d_out;

    void *phh, *pah, *pcsr, *poff, *pcur, *pbs;
    cudaGetSymbolAddress(&phh, g_hh);
    cudaGetSymbolAddress(&pah, g_aggh);
    cudaGetSymbolAddress(&pcsr, g_csr_src);
    cudaGetSymbolAddress(&poff, g_off);
    cudaGetSymbolAddress(&pcur, g_cur);
    cudaGetSymbolAddress(&pbs, g_bsums);
    __half* hbuf = (__half*)phh;
    __half* aggh = (__half*)pah;
    int* csr    = (int*)pcsr;
    int* off    = (int*)poff;
    int* cur    = (int*)pcur;
    int* bsums  = (int*)pbs;

    // ---- CSR build + weight prep + feat->fp16 (constant across layers) ----
    {
        int n4 = (nseg + 3) / 4;
        zero_i4<<<(n4 + 255) / 256, 256>>>((int4*)cur, n4);
        hist_kernel<<<(totE + 255) / 256, 256>>>(dst, cur, E, N);
        int nb = (nseg + CHUNK - 1) / CHUNK;
        scan1_kernel<<<nb, 256>>>(cur, off, bsums, nseg);
        scan2_kernel<<<1, 128>>>(bsums, nb);
        scan3_kernel<<<(nseg + 255) / 256, 256>>>(off, cur, bsums, nseg, totE);
        fill_kernel<<<(totE + 255) / 256, 256>>>(src, dst, cur, csr, E, N);
        prep_kernel<<<(NMATS * 1024 + 255) / 256, 256>>>(W_self, W_neigh);
        int fn4 = N * DIM / 4;
        f2h_kernel<<<(fn4 + 255) / 256, 256>>>((const float4*)feat, (uint2*)hbuf, fn4);
    }

    const int nblocks_gemm = (N + 63) / 64;
    const int agg_blocks = (int)(((long long)nseg * 8 + 255) / 256);

    const __half* h_cur = hbuf;                      // fp16 feat in slot 0
    for (int l = 0; l < NLAYERS; l++) {
        agg_kernel<<<agg_blocks, 256>>>(h_cur, off, csr, aggh, nseg);

        const float* bl = bias + (size_t)l * NTYPES * DIM;
        if (l < NLAYERS - 1) {
            __half* h_next = hbuf + (size_t)((l + 1) & 1) * MAXN * DIM;
            layer_fp16_kernel<<<nblocks_gemm, 256>>>(h_cur, aggh, bl, h_next, N, l * 6);
            h_cur = h_next;
        } else {
            layer_last_fp16_kernel<<<nblocks_gemm, 256>>>(h_cur, aggh, bl, out, N);
        }
    }
}